// round 9
// baseline (speedup 1.0000x reference)
#include <cuda_runtime.h>
#include <cuda_bf16.h>
#include <cstdint>

#define D 64
#define N_MAX 131072
#define E_MAX 2097152

// -------- device scratch --------
__device__ float g_H[N_MAX * D];
__device__ float g_A[N_MAX * D];
__device__ int   g_cnt[N_MAX];
__device__ float g_dinv[N_MAX];
__device__ int   g_rowtmp[N_MAX];
__device__ int   g_rowptr[N_MAX + 1];
__device__ int   g_rank[E_MAX];
__device__ int   g_part[256];
__device__ int2  g_edge[E_MAX];   // {src col, norm bits}
__device__ int   g_elw;           // 1 = int32 edge index, 2 = int64
__device__ int   g_done;

__device__ __forceinline__ float tf32f(float f) {
    uint32_t r;
    asm("cvt.rna.tf32.f32 %0, %1;" : "=r"(r) : "f"(f));
    return __uint_as_float(r);
}

// -------- init + dtype probe --------
__global__ void k_init(const int* __restrict__ p, int n) {
    int i = blockIdx.x * blockDim.x + threadIdx.x;
    if (i < n) g_cnt[i] = 0;
    if (blockIdx.x == 0 && threadIdx.x == 0) {
        g_done = 0;
        int nz = 0;
#pragma unroll
        for (int k = 0; k < 64; k++) nz |= p[2 * k + 1];
        g_elw = (nz == 0) ? 2 : 1;
    }
}

// -------- load helper: 8 edge endpoints at element offset ofs --------
__device__ __forceinline__ void load8(const int* __restrict__ p, long long ofs,
                                      int avail, int elw, int* v) {
    if (elw == 1) {
        if (avail == 8 && ((ofs & 3) == 0)) {
            int4 a = *(const int4*)(p + ofs);
            int4 b = *(const int4*)(p + ofs + 4);
            v[0]=a.x; v[1]=a.y; v[2]=a.z; v[3]=a.w;
            v[4]=b.x; v[5]=b.y; v[6]=b.z; v[7]=b.w;
        } else {
            for (int i = 0; i < 8; i++) v[i] = (i < avail) ? p[ofs + i] : -1;
        }
    } else {
        const long long* q = (const long long*)p;
        if (avail == 8 && ((ofs & 1) == 0)) {
            longlong2 a = *(const longlong2*)(q + ofs);
            longlong2 b = *(const longlong2*)(q + ofs + 2);
            longlong2 c = *(const longlong2*)(q + ofs + 4);
            longlong2 d = *(const longlong2*)(q + ofs + 6);
            v[0]=(int)a.x; v[1]=(int)a.y; v[2]=(int)b.x; v[3]=(int)b.y;
            v[4]=(int)c.x; v[5]=(int)c.y; v[6]=(int)d.x; v[7]=(int)d.y;
        } else {
            for (int i = 0; i < 8; i++) v[i] = (i < avail) ? (int)q[ofs + i] : -1;
        }
    }
}

// -------- degree count + per-edge rank --------
__global__ void k_count(const int* __restrict__ p, int e, int n) {
    int base = (blockIdx.x * blockDim.x + threadIdx.x) * 8;
    if (base >= e) return;
    int elw = g_elw;
    int avail = min(8, e - base);
    int d[8];
    load8(p, (long long)e + base, avail, elw, d);
#pragma unroll
    for (int i = 0; i < 8; i++)
        if ((unsigned)d[i] < (unsigned)n)
            g_rank[base + i] = atomicAdd(&g_cnt[d[i]], 1);
}

// -------- single-pass scan: rowtmp + dinv, last block combines --------
__global__ void __launch_bounds__(1024) k_scan(int n, int e, int nb) {
    __shared__ int wsum[32];
    int i = blockIdx.x * 1024 + threadIdx.x;
    int v = (i < n) ? g_cnt[i] : 0;
    if (i < n) g_dinv[i] = rsqrtf((float)(v + 1));
    int lane = threadIdx.x & 31, w = threadIdx.x >> 5;

    int x = v;
#pragma unroll
    for (int off = 1; off < 32; off <<= 1) {
        int t = __shfl_up_sync(0xffffffffu, x, off);
        if (lane >= off) x += t;
    }
    if (lane == 31) wsum[w] = x;
    __syncthreads();
    if (w == 0) {
        int s = wsum[lane];
        int t = s;
#pragma unroll
        for (int off = 1; off < 32; off <<= 1) {
            int u = __shfl_up_sync(0xffffffffu, t, off);
            if (lane >= off) t += u;
        }
        wsum[lane] = t - s;
        if (lane == 31) g_part[blockIdx.x] = t;
    }
    __syncthreads();
    if (i < n) g_rowtmp[i] = x - v + wsum[w];

    // ticket: last block to finish does the combine
    __threadfence();
    __syncthreads();
    __shared__ int sticket;
    if (threadIdx.x == 0) sticket = atomicAdd(&g_done, 1);
    __syncthreads();
    if (sticket == gridDim.x - 1) {
        __shared__ int sh[128], ex[128];
        int t = threadIdx.x;
        if (t < 128) sh[t] = (t < nb) ? g_part[t] : 0;
        __syncthreads();
#pragma unroll
        for (int off = 1; off < 128; off <<= 1) {
            int u = (t < 128 && t >= off) ? sh[t - off] : 0;
            __syncthreads();
            if (t < 128) sh[t] += u;
            __syncthreads();
        }
        if (t < 128) ex[t] = sh[t] - ((t < nb) ? g_part[t] : 0);
        __syncthreads();
        for (int j = t; j < n; j += 1024)
            g_rowptr[j] = g_rowtmp[j] + ex[j >> 10];
        if (t == 0) g_rowptr[n] = e;
    }
}

// -------- CSR fill: no atomics (uses precomputed rank) --------
__global__ void k_fill(const int* __restrict__ p, int e, int n) {
    int base = (blockIdx.x * blockDim.x + threadIdx.x) * 8;
    if (base >= e) return;
    int elw = g_elw;
    int avail = min(8, e - base);
    int s[8], d[8];
    load8(p, (long long)base, avail, elw, s);
    load8(p, (long long)e + base, avail, elw, d);
#pragma unroll
    for (int i = 0; i < 8; i++) {
        if ((unsigned)s[i] < (unsigned)n && (unsigned)d[i] < (unsigned)n) {
            int pos = g_rowptr[d[i]] + g_rank[base + i];
            float nrm = g_dinv[s[i]] * g_dinv[d[i]];
            g_edge[pos] = make_int2(s[i], __float_as_int(nrm));
        }
    }
}

// -------- GEMM0: g_H = x @ W0 (tf32 mma) --------
__global__ void __launch_bounds__(128) k_gemm0(const float* __restrict__ A,
                                               const float* __restrict__ W, int n) {
    __shared__ float As[64][68];
    __shared__ float Ws[64][72];
    int tid = threadIdx.x;
    int rowbase = blockIdx.x * 64;

#pragma unroll
    for (int i = 0; i < 8; i++) {
        int idx = tid + i * 128;
        int r = idx >> 4, f4 = idx & 15;
        float4 va = (rowbase + r < n)
            ? *(const float4*)(A + (size_t)(rowbase + r) * 64 + f4 * 4)
            : make_float4(0.f, 0.f, 0.f, 0.f);
        As[r][f4 * 4 + 0] = tf32f(va.x); As[r][f4 * 4 + 1] = tf32f(va.y);
        As[r][f4 * 4 + 2] = tf32f(va.z); As[r][f4 * 4 + 3] = tf32f(va.w);
        float4 vw = *(const float4*)(W + r * 64 + f4 * 4);
        Ws[r][f4 * 4 + 0] = tf32f(vw.x); Ws[r][f4 * 4 + 1] = tf32f(vw.y);
        Ws[r][f4 * 4 + 2] = tf32f(vw.z); Ws[r][f4 * 4 + 3] = tf32f(vw.w);
    }
    __syncthreads();

    int warp = tid >> 5, lane = tid & 31;
    int gid = lane >> 2, tig = lane & 3;
    int ar0 = warp * 16 + gid, ar1 = ar0 + 8;

    float acc[8][4];
#pragma unroll
    for (int t = 0; t < 8; t++)
#pragma unroll
        for (int c = 0; c < 4; c++) acc[t][c] = 0.f;

#pragma unroll
    for (int ks = 0; ks < 8; ks++) {
        int k0 = ks * 8;
        uint32_t a0 = __float_as_uint(As[ar0][k0 + tig]);
        uint32_t a1 = __float_as_uint(As[ar1][k0 + tig]);
        uint32_t a2 = __float_as_uint(As[ar0][k0 + tig + 4]);
        uint32_t a3 = __float_as_uint(As[ar1][k0 + tig + 4]);
#pragma unroll
        for (int nt = 0; nt < 8; nt++) {
            uint32_t b0 = __float_as_uint(Ws[k0 + tig][nt * 8 + gid]);
            uint32_t b1 = __float_as_uint(Ws[k0 + tig + 4][nt * 8 + gid]);
            asm volatile(
                "mma.sync.aligned.m16n8k8.row.col.f32.tf32.tf32.f32 "
                "{%0,%1,%2,%3}, {%4,%5,%6,%7}, {%8,%9}, {%0,%1,%2,%3};"
                : "+f"(acc[nt][0]), "+f"(acc[nt][1]), "+f"(acc[nt][2]), "+f"(acc[nt][3])
                : "r"(a0), "r"(a1), "r"(a2), "r"(a3), "r"(b0), "r"(b1));
        }
    }

    int row0 = rowbase + warp * 16 + gid, row1 = row0 + 8;
#pragma unroll
    for (int nt = 0; nt < 8; nt++) {
        int col = nt * 8 + tig * 2;
        if (row0 < n)
            *(float2*)(g_H + (size_t)row0 * 64 + col) = make_float2(acc[nt][0], acc[nt][1]);
        if (row1 < n)
            *(float2*)(g_H + (size_t)row1 * 64 + col) = make_float2(acc[nt][2], acc[nt][3]);
    }
}

// -------- Fused agg + next GEMM --------
// DIR=0: HIN=g_H, HOUT=g_A.  DIR=1: HIN=g_A, HOUT=g_H.
// Block: 256 thr = 8 warps. Warp w aggregates nodes rowbase+8w..+7 into smem As
// (bias+relu+tf32), then warps 0-3 do the 64x64x64 mma and write HOUT.
template <int DIR>
__global__ void __launch_bounds__(256) k_agg_gemm(const float* __restrict__ bias,
                                                  const float* __restrict__ W, int n) {
    __shared__ float As[64][68];
    __shared__ float Ws[64][72];
    const float* HIN = (DIR == 0) ? (const float*)g_H : (const float*)g_A;
    float* HOUT      = (DIR == 0) ? (float*)g_A : (float*)g_H;
    int tid = threadIdx.x;
    int rowbase = blockIdx.x * 64;

    // stage W
#pragma unroll
    for (int i = 0; i < 4; i++) {
        int idx = tid + i * 256;
        int r = idx >> 4, f4 = idx & 15;
        float4 vw = *(const float4*)(W + r * 64 + f4 * 4);
        Ws[r][f4 * 4 + 0] = tf32f(vw.x); Ws[r][f4 * 4 + 1] = tf32f(vw.y);
        Ws[r][f4 * 4 + 2] = tf32f(vw.z); Ws[r][f4 * 4 + 3] = tf32f(vw.w);
    }

    int warp = tid >> 5, lane = tid & 31;
    const float2* H2 = (const float2*)HIN;
    float2 bb = ((const float2*)bias)[lane];

    // phase 1: aggregate 8 nodes per warp
    for (int r8 = 0; r8 < 8; r8++) {
        int li = warp * 8 + r8;
        int i = rowbase + li;
        if (i < n) {
            float di = g_dinv[i];
            float sn = di * di;
            float2 h = H2[i * 32 + lane];
            float2 acc = make_float2(h.x * sn, h.y * sn);
            int s = g_rowptr[i], e = g_rowptr[i + 1];
            for (int base = s; base < e; base += 32) {
                int m = min(32, e - base);
                int c = 0; float nv = 0.f;
                if (lane < m) {
                    int2 ed = g_edge[base + lane];
                    c = ed.x; nv = __int_as_float(ed.y);
                }
#pragma unroll 4
                for (int j = 0; j < m; j++) {
                    int   cj = __shfl_sync(0xffffffffu, c, j);
                    float nj = __shfl_sync(0xffffffffu, nv, j);
                    float2 hh = __ldg(&H2[cj * 32 + lane]);
                    acc.x += hh.x * nj;
                    acc.y += hh.y * nj;
                }
            }
            acc.x = fmaxf(acc.x + bb.x, 0.f);
            acc.y = fmaxf(acc.y + bb.y, 0.f);
            As[li][2 * lane]     = tf32f(acc.x);
            As[li][2 * lane + 1] = tf32f(acc.y);
        } else {
            As[li][2 * lane] = 0.f;
            As[li][2 * lane + 1] = 0.f;
        }
    }
    __syncthreads();

    // phase 2: mma on warps 0-3
    if (warp < 4) {
        int gid = lane >> 2, tig = lane & 3;
        int ar0 = warp * 16 + gid, ar1 = ar0 + 8;
        float acc[8][4];
#pragma unroll
        for (int t = 0; t < 8; t++)
#pragma unroll
            for (int c = 0; c < 4; c++) acc[t][c] = 0.f;

#pragma unroll
        for (int ks = 0; ks < 8; ks++) {
            int k0 = ks * 8;
            uint32_t a0 = __float_as_uint(As[ar0][k0 + tig]);
            uint32_t a1 = __float_as_uint(As[ar1][k0 + tig]);
            uint32_t a2 = __float_as_uint(As[ar0][k0 + tig + 4]);
            uint32_t a3 = __float_as_uint(As[ar1][k0 + tig + 4]);
#pragma unroll
            for (int nt = 0; nt < 8; nt++) {
                uint32_t b0 = __float_as_uint(Ws[k0 + tig][nt * 8 + gid]);
                uint32_t b1 = __float_as_uint(Ws[k0 + tig + 4][nt * 8 + gid]);
                asm volatile(
                    "mma.sync.aligned.m16n8k8.row.col.f32.tf32.tf32.f32 "
                    "{%0,%1,%2,%3}, {%4,%5,%6,%7}, {%8,%9}, {%0,%1,%2,%3};"
                    : "+f"(acc[nt][0]), "+f"(acc[nt][1]), "+f"(acc[nt][2]), "+f"(acc[nt][3])
                    : "r"(a0), "r"(a1), "r"(a2), "r"(a3), "r"(b0), "r"(b1));
            }
        }

        int row0 = rowbase + warp * 16 + gid, row1 = row0 + 8;
#pragma unroll
        for (int nt = 0; nt < 8; nt++) {
            int col = nt * 8 + tig * 2;
            if (row0 < n)
                *(float2*)(HOUT + (size_t)row0 * 64 + col) = make_float2(acc[nt][0], acc[nt][1]);
            if (row1 < n)
                *(float2*)(HOUT + (size_t)row1 * 64 + col) = make_float2(acc[nt][2], acc[nt][3]);
        }
    }
}

// -------- Final aggregation (reads g_H, writes external out) --------
__global__ void k_agg_out(const float* __restrict__ bias, float* __restrict__ outext,
                          int n) {
    int gw = (blockIdx.x * blockDim.x + threadIdx.x) >> 5;
    int lane = threadIdx.x & 31;
    if (gw >= n) return;
    int i = gw;

    const float2* H2 = (const float2*)g_H;
    float di = g_dinv[i];
    float sn = di * di;
    float2 h = H2[i * 32 + lane];
    float2 acc = make_float2(h.x * sn, h.y * sn);

    int s = g_rowptr[i], e = g_rowptr[i + 1];
    for (int base = s; base < e; base += 32) {
        int m = min(32, e - base);
        int c = 0; float nv = 0.f;
        if (lane < m) {
            int2 ed = g_edge[base + lane];
            c = ed.x; nv = __int_as_float(ed.y);
        }
#pragma unroll 4
        for (int j = 0; j < m; j++) {
            int   cj = __shfl_sync(0xffffffffu, c, j);
            float nj = __shfl_sync(0xffffffffu, nv, j);
            float2 hh = __ldg(&H2[cj * 32 + lane]);
            acc.x += hh.x * nj;
            acc.y += hh.y * nj;
        }
    }
    float2 bb = ((const float2*)bias)[lane];
    acc.x = fmaxf(acc.x + bb.x, 0.f);
    acc.y = fmaxf(acc.y + bb.y, 0.f);
    ((float2*)outext)[i * 32 + lane] = acc;
}

// -------- launch --------
extern "C" void kernel_launch(void* const* d_in, const int* in_sizes, int n_in,
                              void* d_out, int out_size) {
    const float* x  = (const float*)d_in[0];
    const int*   ei = (const int*)d_in[1];
    const float* W0 = (const float*)d_in[2];
    const float* b0 = (const float*)d_in[3];
    const float* W1 = (const float*)d_in[4];
    const float* b1 = (const float*)d_in[5];
    const float* W2 = (const float*)d_in[6];
    const float* b2 = (const float*)d_in[7];
    float* out = (float*)d_out;

    int n = in_sizes[0] / D;
    int e = in_sizes[1] / 2;
    int nb = (n + 1023) / 1024;
    int e8 = (e + 7) / 8;

    static cudaStream_t s2 = nullptr;
    static cudaEvent_t ev_fork = nullptr, ev_g0 = nullptr;
    if (!s2) {
        cudaStreamCreateWithFlags(&s2, cudaStreamNonBlocking);
        cudaEventCreateWithFlags(&ev_fork, cudaEventDisableTiming);
        cudaEventCreateWithFlags(&ev_g0, cudaEventDisableTiming);
    }

    int tile_blocks = (n + 63) / 64;
    int agg_blocks  = (n + 7) / 8;

    // fork: GEMM0 (x @ W0 -> g_H) independent of CSR build
    cudaEventRecord(ev_fork, 0);
    cudaStreamWaitEvent(s2, ev_fork, 0);
    k_gemm0<<<tile_blocks, 128, 0, s2>>>(x, W0, n);
    cudaEventRecord(ev_g0, s2);

    // CSR build on main stream
    k_init <<<(n + 255) / 256, 256>>>(ei, n);
    k_count<<<(e8 + 255) / 256, 256>>>(ei, e, n);
    k_scan <<<nb, 1024>>>(n, e, nb);
    k_fill <<<(e8 + 255) / 256, 256>>>(ei, e, n);

    // join, then fused layers
    cudaStreamWaitEvent(0, ev_g0, 0);
    k_agg_gemm<0><<<tile_blocks, 256>>>(b0, W1, n);   // agg(H)->A0, A0@W1 -> g_A
    k_agg_gemm<1><<<tile_blocks, 256>>>(b1, W2, n);   // agg(g_A)->A1, A1@W2 -> g_H
    k_agg_out   <<<agg_blocks, 256>>>(b2, out, n);    // agg(g_H)+b2 -> out
}

// round 10
// speedup vs baseline: 1.1351x; 1.1351x over previous
#include <cuda_runtime.h>
#include <cuda_bf16.h>
#include <cstdint>

#define D 64
#define N_MAX 131072
#define E_MAX 2097152

// -------- device scratch --------
__device__ float g_H[N_MAX * D];
__device__ float g_A[N_MAX * D];
__device__ int   g_cnt[N_MAX];
__device__ float g_dinv[N_MAX];
__device__ int   g_rowtmp[N_MAX];
__device__ int   g_rowptr[N_MAX + 1];
__device__ int   g_rank[E_MAX];
__device__ int   g_part[256];
__device__ int2  g_edge[E_MAX];   // {src col, norm bits}
__device__ int   g_elw;           // 1 = int32 edge index, 2 = int64

__device__ __forceinline__ float tf32f(float f) {
    uint32_t r;
    asm("cvt.rna.tf32.f32 %0, %1;" : "=r"(r) : "f"(f));
    return __uint_as_float(r);
}

// -------- init + dtype probe --------
__global__ void k_init(const int* __restrict__ p, int n) {
    int i = blockIdx.x * blockDim.x + threadIdx.x;
    if (i < n) g_cnt[i] = 0;
    if (blockIdx.x == 0 && threadIdx.x == 0) {
        int nz = 0;
#pragma unroll
        for (int k = 0; k < 64; k++) nz |= p[2 * k + 1];
        g_elw = (nz == 0) ? 2 : 1;
    }
}

// -------- load helper: 8 edge endpoints at element offset ofs --------
__device__ __forceinline__ void load8(const int* __restrict__ p, long long ofs,
                                      int avail, int elw, int* v) {
    if (elw == 1) {
        if (avail == 8 && ((ofs & 3) == 0)) {
            int4 a = *(const int4*)(p + ofs);
            int4 b = *(const int4*)(p + ofs + 4);
            v[0]=a.x; v[1]=a.y; v[2]=a.z; v[3]=a.w;
            v[4]=b.x; v[5]=b.y; v[6]=b.z; v[7]=b.w;
        } else {
            for (int i = 0; i < 8; i++) v[i] = (i < avail) ? p[ofs + i] : -1;
        }
    } else {
        const long long* q = (const long long*)p;
        if (avail == 8 && ((ofs & 1) == 0)) {
            longlong2 a = *(const longlong2*)(q + ofs);
            longlong2 b = *(const longlong2*)(q + ofs + 2);
            longlong2 c = *(const longlong2*)(q + ofs + 4);
            longlong2 d = *(const longlong2*)(q + ofs + 6);
            v[0]=(int)a.x; v[1]=(int)a.y; v[2]=(int)b.x; v[3]=(int)b.y;
            v[4]=(int)c.x; v[5]=(int)c.y; v[6]=(int)d.x; v[7]=(int)d.y;
        } else {
            for (int i = 0; i < 8; i++) v[i] = (i < avail) ? (int)q[ofs + i] : -1;
        }
    }
}

// -------- degree count + per-edge rank --------
__global__ void k_count(const int* __restrict__ p, int e, int n) {
    int base = (blockIdx.x * blockDim.x + threadIdx.x) * 8;
    if (base >= e) return;
    int elw = g_elw;
    int avail = min(8, e - base);
    int d[8];
    load8(p, (long long)e + base, avail, elw, d);
#pragma unroll
    for (int i = 0; i < 8; i++)
        if ((unsigned)d[i] < (unsigned)n)
            g_rank[base + i] = atomicAdd(&g_cnt[d[i]], 1);
}

// -------- scan A: warp-shuffle block scan + dinv --------
__global__ void __launch_bounds__(1024) k_scanA(int n) {
    __shared__ int wsum[32];
    int i = blockIdx.x * 1024 + threadIdx.x;
    int v = (i < n) ? g_cnt[i] : 0;
    if (i < n) g_dinv[i] = rsqrtf((float)(v + 1));
    int lane = threadIdx.x & 31, w = threadIdx.x >> 5;

    int x = v;
#pragma unroll
    for (int off = 1; off < 32; off <<= 1) {
        int t = __shfl_up_sync(0xffffffffu, x, off);
        if (lane >= off) x += t;
    }
    if (lane == 31) wsum[w] = x;
    __syncthreads();
    if (w == 0) {
        int s = wsum[lane];
        int t = s;
#pragma unroll
        for (int off = 1; off < 32; off <<= 1) {
            int u = __shfl_up_sync(0xffffffffu, t, off);
            if (lane >= off) t += u;
        }
        wsum[lane] = t - s;
        if (lane == 31) g_part[blockIdx.x] = t;
    }
    __syncthreads();
    if (i < n) g_rowtmp[i] = x - v + wsum[w];
}

// -------- scan C: local scan of partials --------
__global__ void k_scanC(int n, int e, int nb) {
    __shared__ int sh[128];
    __shared__ int ex[128];
    int t = threadIdx.x & 127;
    int v = (t < nb) ? g_part[t] : 0;
    sh[t] = v;
    __syncthreads();
#pragma unroll
    for (int off = 1; off < 128; off <<= 1) {
        int u = (t >= off) ? sh[t - off] : 0;
        __syncthreads();
        sh[t] += u;
        __syncthreads();
    }
    ex[t] = sh[t] - v;
    __syncthreads();

    int i = blockIdx.x * blockDim.x + threadIdx.x;
    if (i < n) g_rowptr[i] = g_rowtmp[i] + ex[i >> 10];
    if (i == 0) g_rowptr[n] = e;
}

// -------- CSR fill: atomic-free (uses precomputed rank) --------
__global__ void k_fill(const int* __restrict__ p, int e, int n) {
    int base = (blockIdx.x * blockDim.x + threadIdx.x) * 8;
    if (base >= e) return;
    int elw = g_elw;
    int avail = min(8, e - base);
    int s[8], d[8];
    load8(p, (long long)base, avail, elw, s);
    load8(p, (long long)e + base, avail, elw, d);
#pragma unroll
    for (int i = 0; i < 8; i++) {
        if ((unsigned)s[i] < (unsigned)n && (unsigned)d[i] < (unsigned)n) {
            int pos = g_rowptr[d[i]] + g_rank[base + i];
            float nrm = g_dinv[s[i]] * g_dinv[d[i]];
            g_edge[pos] = make_int2(s[i], __float_as_int(nrm));
        }
    }
}

// -------- GEMM: g_H[n,64] = A[n,64] @ W[64,64] via tf32 mma.sync --------
template <int SRC>
__global__ void __launch_bounds__(128) k_gemm(const float* __restrict__ Aext,
                                              const float* __restrict__ W, int n) {
    __shared__ float As[64][68];
    __shared__ float Ws[64][72];

    const float* A = (SRC == 0) ? Aext : (const float*)g_A;
    int tid = threadIdx.x;
    int rowbase = blockIdx.x * 64;

#pragma unroll
    for (int i = 0; i < 8; i++) {
        int idx = tid + i * 128;
        int r = idx >> 4, f4 = idx & 15;
        float4 va = (rowbase + r < n)
            ? *(const float4*)(A + (size_t)(rowbase + r) * 64 + f4 * 4)
            : make_float4(0.f, 0.f, 0.f, 0.f);
        As[r][f4 * 4 + 0] = tf32f(va.x); As[r][f4 * 4 + 1] = tf32f(va.y);
        As[r][f4 * 4 + 2] = tf32f(va.z); As[r][f4 * 4 + 3] = tf32f(va.w);
        float4 vw = *(const float4*)(W + r * 64 + f4 * 4);
        Ws[r][f4 * 4 + 0] = tf32f(vw.x); Ws[r][f4 * 4 + 1] = tf32f(vw.y);
        Ws[r][f4 * 4 + 2] = tf32f(vw.z); Ws[r][f4 * 4 + 3] = tf32f(vw.w);
    }
    __syncthreads();

    int warp = tid >> 5, lane = tid & 31;
    int gid = lane >> 2, tig = lane & 3;
    int ar0 = warp * 16 + gid, ar1 = ar0 + 8;

    float acc[8][4];
#pragma unroll
    for (int t = 0; t < 8; t++)
#pragma unroll
        for (int c = 0; c < 4; c++) acc[t][c] = 0.f;

#pragma unroll
    for (int ks = 0; ks < 8; ks++) {
        int k0 = ks * 8;
        uint32_t a0 = __float_as_uint(As[ar0][k0 + tig]);
        uint32_t a1 = __float_as_uint(As[ar1][k0 + tig]);
        uint32_t a2 = __float_as_uint(As[ar0][k0 + tig + 4]);
        uint32_t a3 = __float_as_uint(As[ar1][k0 + tig + 4]);
#pragma unroll
        for (int nt = 0; nt < 8; nt++) {
            uint32_t b0 = __float_as_uint(Ws[k0 + tig][nt * 8 + gid]);
            uint32_t b1 = __float_as_uint(Ws[k0 + tig + 4][nt * 8 + gid]);
            asm volatile(
                "mma.sync.aligned.m16n8k8.row.col.f32.tf32.tf32.f32 "
                "{%0,%1,%2,%3}, {%4,%5,%6,%7}, {%8,%9}, {%0,%1,%2,%3};"
                : "+f"(acc[nt][0]), "+f"(acc[nt][1]), "+f"(acc[nt][2]), "+f"(acc[nt][3])
                : "r"(a0), "r"(a1), "r"(a2), "r"(a3), "r"(b0), "r"(b1));
        }
    }

    int row0 = rowbase + warp * 16 + gid, row1 = row0 + 8;
#pragma unroll
    for (int nt = 0; nt < 8; nt++) {
        int col = nt * 8 + tig * 2;
        if (row0 < n)
            *(float2*)(g_H + (size_t)row0 * 64 + col) = make_float2(acc[nt][0], acc[nt][1]);
        if (row1 < n)
            *(float2*)(g_H + (size_t)row1 * 64 + col) = make_float2(acc[nt][2], acc[nt][3]);
    }
}

// -------- Aggregation (warp per node, float2, int2 edge payload) --------
template <int DSTOUT>
__global__ void k_agg(const float* __restrict__ bias, float* __restrict__ outext,
                      int n) {
    int gw = (blockIdx.x * blockDim.x + threadIdx.x) >> 5;
    int lane = threadIdx.x & 31;
    if (gw >= n) return;
    int i = gw;

    const float2* H2 = (const float2*)g_H;
    float di = g_dinv[i];
    float sn = di * di;
    float2 h = H2[i * 32 + lane];
    float2 acc = make_float2(h.x * sn, h.y * sn);

    int s = g_rowptr[i], e = g_rowptr[i + 1];
    for (int base = s; base < e; base += 32) {
        int m = min(32, e - base);
        int c = 0; float nv = 0.f;
        if (lane < m) {
            int2 ed = g_edge[base + lane];
            c = ed.x; nv = __int_as_float(ed.y);
        }
#pragma unroll 4
        for (int j = 0; j < m; j++) {
            int   cj = __shfl_sync(0xffffffffu, c, j);
            float nj = __shfl_sync(0xffffffffu, nv, j);
            float2 hh = __ldg(&H2[cj * 32 + lane]);
            acc.x += hh.x * nj;
            acc.y += hh.y * nj;
        }
    }
    float2 bb = ((const float2*)bias)[lane];
    acc.x = fmaxf(acc.x + bb.x, 0.f);
    acc.y = fmaxf(acc.y + bb.y, 0.f);
    float2* outp = (DSTOUT == 0) ? (float2*)g_A : (float2*)outext;
    outp[i * 32 + lane] = acc;
}

// -------- launch --------
extern "C" void kernel_launch(void* const* d_in, const int* in_sizes, int n_in,
                              void* d_out, int out_size) {
    const float* x  = (const float*)d_in[0];
    const int*   ei = (const int*)d_in[1];
    const float* W0 = (const float*)d_in[2];
    const float* b0 = (const float*)d_in[3];
    const float* W1 = (const float*)d_in[4];
    const float* b1 = (const float*)d_in[5];
    const float* W2 = (const float*)d_in[6];
    const float* b2 = (const float*)d_in[7];
    float* out = (float*)d_out;

    int n = in_sizes[0] / D;
    int e = in_sizes[1] / 2;
    int nb = (n + 1023) / 1024;
    int e8 = (e + 7) / 8;

    int tile_blocks = (n + 63) / 64;
    int agg_blocks  = (n + 7) / 8;

    k_init <<<(n + 255) / 256, 256>>>(ei, n);
    k_count<<<(e8 + 255) / 256, 256>>>(ei, e, n);
    k_scanA<<<nb, 1024>>>(n);
    k_scanC<<<(n + 255) / 256, 256>>>(n, e, nb);
    k_fill <<<(e8 + 255) / 256, 256>>>(ei, e, n);

    k_gemm<0><<<tile_blocks, 128>>>(x, W0, n);
    k_agg<0> <<<agg_blocks, 256>>>(b0, nullptr, n);
    k_gemm<1><<<tile_blocks, 128>>>(nullptr, W1, n);
    k_agg<0> <<<agg_blocks, 256>>>(b1, nullptr, n);
    k_gemm<1><<<tile_blocks, 128>>>(nullptr, W2, n);
    k_agg<1> <<<agg_blocks, 256>>>(b2, out, n);
}

// round 11
// speedup vs baseline: 1.3027x; 1.1476x over previous
#include <cuda_runtime.h>
#include <cuda_bf16.h>
#include <cstdint>

#define D 64
#define N_MAX 131072
#define E_MAX 2097152

// -------- device scratch --------
__device__ float g_H[N_MAX * D];
__device__ float g_A[N_MAX * D];
__device__ int   g_cnt[N_MAX];      // statically zero; re-zeroed by k_scanA each run
__device__ float g_dinv[N_MAX];
__device__ int   g_rowtmp[N_MAX];
__device__ int   g_rowptr[N_MAX + 1];
__device__ int   g_cursor[N_MAX];   // seeded to rowptr by k_scanC each run
__device__ int   g_part[256];
__device__ int2  g_edge[E_MAX];     // {src col, dinv[src] bits}

__device__ __forceinline__ float tf32f(float f) {
    uint32_t r;
    asm("cvt.rna.tf32.f32 %0, %1;" : "=r"(r) : "f"(f));
    return __uint_as_float(r);
}

// per-block edge dtype probe: int64 buffer (values < 2^31) has zero odd slots
__device__ __forceinline__ int probe_elw(const int* __restrict__ p) {
    int nz = 0;
#pragma unroll
    for (int k = 0; k < 16; k++) nz |= p[2 * k + 1];
    return nz ? 1 : 2;
}

// -------- degree count: 4 edges/thread, REDG (no return) --------
__global__ void k_count(const int* __restrict__ p, int e, int n) {
    __shared__ int selw;
    if (threadIdx.x == 0) selw = probe_elw(p);
    __syncthreads();
    int elw = selw;
    int base = (blockIdx.x * blockDim.x + threadIdx.x) * 4;
    if (base >= e) return;
    int d[4];
    bool full = (base + 3 < e) && ((e & 3) == 0);
    if (elw == 1) {
        if (full) {
            int4 v = *(const int4*)(p + e + base);
            d[0] = v.x; d[1] = v.y; d[2] = v.z; d[3] = v.w;
        } else {
            for (int i = 0; i < 4; i++) d[i] = (base + i < e) ? p[e + base + i] : -1;
        }
    } else {
        const long long* q = (const long long*)p;
        if (full) {
            longlong2 v0 = *(const longlong2*)(q + e + base);
            longlong2 v1 = *(const longlong2*)(q + e + base + 2);
            d[0] = (int)v0.x; d[1] = (int)v0.y; d[2] = (int)v1.x; d[3] = (int)v1.y;
        } else {
            for (int i = 0; i < 4; i++) d[i] = (base + i < e) ? (int)q[e + base + i] : -1;
        }
    }
#pragma unroll
    for (int i = 0; i < 4; i++)
        if ((unsigned)d[i] < (unsigned)n) atomicAdd(&g_cnt[d[i]], 1);
}

// -------- scan A: warp-shuffle block scan + dinv + cnt reset --------
__global__ void __launch_bounds__(1024) k_scanA(int n) {
    __shared__ int wsum[32];
    int i = blockIdx.x * 1024 + threadIdx.x;
    int v = (i < n) ? g_cnt[i] : 0;
    if (i < n) {
        g_dinv[i] = rsqrtf((float)(v + 1));
        g_cnt[i] = 0;   // reset for next graph replay
    }
    int lane = threadIdx.x & 31, w = threadIdx.x >> 5;

    int x = v;
#pragma unroll
    for (int off = 1; off < 32; off <<= 1) {
        int t = __shfl_up_sync(0xffffffffu, x, off);
        if (lane >= off) x += t;
    }
    if (lane == 31) wsum[w] = x;
    __syncthreads();
    if (w == 0) {
        int s = wsum[lane];
        int t = s;
#pragma unroll
        for (int off = 1; off < 32; off <<= 1) {
            int u = __shfl_up_sync(0xffffffffu, t, off);
            if (lane >= off) t += u;
        }
        wsum[lane] = t - s;
        if (lane == 31) g_part[blockIdx.x] = t;
    }
    __syncthreads();
    if (i < n) g_rowtmp[i] = x - v + wsum[w];
}

// -------- scan C: local scan of partials; writes rowptr AND cursor --------
__global__ void k_scanC(int n, int e, int nb) {
    __shared__ int sh[128];
    __shared__ int ex[128];
    int t = threadIdx.x & 127;
    int v = (t < nb) ? g_part[t] : 0;
    sh[t] = v;
    __syncthreads();
#pragma unroll
    for (int off = 1; off < 128; off <<= 1) {
        int u = (t >= off) ? sh[t - off] : 0;
        __syncthreads();
        sh[t] += u;
        __syncthreads();
    }
    ex[t] = sh[t] - v;
    __syncthreads();

    int i = blockIdx.x * blockDim.x + threadIdx.x;
    if (i < n) {
        int rp = g_rowtmp[i] + ex[i >> 10];
        g_rowptr[i] = rp;
        g_cursor[i] = rp;   // cursor starts at row base: fill needs no rowptr gather
    }
    if (i == 0) g_rowptr[n] = e;
}

// -------- CSR fill: 4 edges/thread; single atomic per edge; stores dinv[src] --------
__global__ void k_fill(const int* __restrict__ p, int e, int n) {
    __shared__ int selw;
    if (threadIdx.x == 0) selw = probe_elw(p);
    __syncthreads();
    int elw = selw;
    int base = (blockIdx.x * blockDim.x + threadIdx.x) * 4;
    if (base >= e) return;
    int s[4], d[4];
    bool full = (base + 3 < e) && ((e & 3) == 0);
    if (elw == 1) {
        if (full) {
            int4 vs = *(const int4*)(p + base);
            int4 vd = *(const int4*)(p + e + base);
            s[0] = vs.x; s[1] = vs.y; s[2] = vs.z; s[3] = vs.w;
            d[0] = vd.x; d[1] = vd.y; d[2] = vd.z; d[3] = vd.w;
        } else {
            for (int i = 0; i < 4; i++) {
                s[i] = (base + i < e) ? p[base + i] : -1;
                d[i] = (base + i < e) ? p[e + base + i] : -1;
            }
        }
    } else {
        const long long* q = (const long long*)p;
        if (full) {
            longlong2 s0 = *(const longlong2*)(q + base);
            longlong2 s1 = *(const longlong2*)(q + base + 2);
            longlong2 d0 = *(const longlong2*)(q + e + base);
            longlong2 d1 = *(const longlong2*)(q + e + base + 2);
            s[0] = (int)s0.x; s[1] = (int)s0.y; s[2] = (int)s1.x; s[3] = (int)s1.y;
            d[0] = (int)d0.x; d[1] = (int)d0.y; d[2] = (int)d1.x; d[3] = (int)d1.y;
        } else {
            for (int i = 0; i < 4; i++) {
                s[i] = (base + i < e) ? (int)q[base + i] : -1;
                d[i] = (base + i < e) ? (int)q[e + base + i] : -1;
            }
        }
    }
#pragma unroll
    for (int i = 0; i < 4; i++) {
        if ((unsigned)s[i] < (unsigned)n && (unsigned)d[i] < (unsigned)n) {
            int pos = atomicAdd(&g_cursor[d[i]], 1);
            g_edge[pos] = make_int2(s[i], __float_as_int(g_dinv[s[i]]));
        }
    }
}

// -------- GEMM: g_H[n,64] = A[n,64] @ W[64,64] via tf32 mma.sync --------
template <int SRC>
__global__ void __launch_bounds__(128) k_gemm(const float* __restrict__ Aext,
                                              const float* __restrict__ W, int n) {
    __shared__ float As[64][68];
    __shared__ float Ws[64][72];

    const float* A = (SRC == 0) ? Aext : (const float*)g_A;
    int tid = threadIdx.x;
    int rowbase = blockIdx.x * 64;

#pragma unroll
    for (int i = 0; i < 8; i++) {
        int idx = tid + i * 128;
        int r = idx >> 4, f4 = idx & 15;
        float4 va = (rowbase + r < n)
            ? *(const float4*)(A + (size_t)(rowbase + r) * 64 + f4 * 4)
            : make_float4(0.f, 0.f, 0.f, 0.f);
        As[r][f4 * 4 + 0] = tf32f(va.x); As[r][f4 * 4 + 1] = tf32f(va.y);
        As[r][f4 * 4 + 2] = tf32f(va.z); As[r][f4 * 4 + 3] = tf32f(va.w);
        float4 vw = *(const float4*)(W + r * 64 + f4 * 4);
        Ws[r][f4 * 4 + 0] = tf32f(vw.x); Ws[r][f4 * 4 + 1] = tf32f(vw.y);
        Ws[r][f4 * 4 + 2] = tf32f(vw.z); Ws[r][f4 * 4 + 3] = tf32f(vw.w);
    }
    __syncthreads();

    int warp = tid >> 5, lane = tid & 31;
    int gid = lane >> 2, tig = lane & 3;
    int ar0 = warp * 16 + gid, ar1 = ar0 + 8;

    float acc[8][4];
#pragma unroll
    for (int t = 0; t < 8; t++)
#pragma unroll
        for (int c = 0; c < 4; c++) acc[t][c] = 0.f;

#pragma unroll
    for (int ks = 0; ks < 8; ks++) {
        int k0 = ks * 8;
        uint32_t a0 = __float_as_uint(As[ar0][k0 + tig]);
        uint32_t a1 = __float_as_uint(As[ar1][k0 + tig]);
        uint32_t a2 = __float_as_uint(As[ar0][k0 + tig + 4]);
        uint32_t a3 = __float_as_uint(As[ar1][k0 + tig + 4]);
#pragma unroll
        for (int nt = 0; nt < 8; nt++) {
            uint32_t b0 = __float_as_uint(Ws[k0 + tig][nt * 8 + gid]);
            uint32_t b1 = __float_as_uint(Ws[k0 + tig + 4][nt * 8 + gid]);
            asm volatile(
                "mma.sync.aligned.m16n8k8.row.col.f32.tf32.tf32.f32 "
                "{%0,%1,%2,%3}, {%4,%5,%6,%7}, {%8,%9}, {%0,%1,%2,%3};"
                : "+f"(acc[nt][0]), "+f"(acc[nt][1]), "+f"(acc[nt][2]), "+f"(acc[nt][3])
                : "r"(a0), "r"(a1), "r"(a2), "r"(a3), "r"(b0), "r"(b1));
        }
    }

    int row0 = rowbase + warp * 16 + gid, row1 = row0 + 8;
#pragma unroll
    for (int nt = 0; nt < 8; nt++) {
        int col = nt * 8 + tig * 2;
        if (row0 < n)
            *(float2*)(g_H + (size_t)row0 * 64 + col) = make_float2(acc[nt][0], acc[nt][1]);
        if (row1 < n)
            *(float2*)(g_H + (size_t)row1 * 64 + col) = make_float2(acc[nt][2], acc[nt][3]);
    }
}

// -------- Aggregation (warp per node; edge carries dinv[src], scaled by di here) --------
template <int DSTOUT>
__global__ void k_agg(const float* __restrict__ bias, float* __restrict__ outext,
                      int n) {
    int gw = (blockIdx.x * blockDim.x + threadIdx.x) >> 5;
    int lane = threadIdx.x & 31;
    if (gw >= n) return;
    int i = gw;

    const float2* H2 = (const float2*)g_H;
    float di = g_dinv[i];
    float sn = di * di;
    float2 h = H2[i * 32 + lane];
    float2 acc = make_float2(h.x * sn, h.y * sn);

    int s = g_rowptr[i], e = g_rowptr[i + 1];
    for (int base = s; base < e; base += 32) {
        int m = min(32, e - base);
        int c = 0; float nv = 0.f;
        if (lane < m) {
            int2 ed = g_edge[base + lane];
            c = ed.x; nv = __int_as_float(ed.y);   // dinv[src]
        }
#pragma unroll 4
        for (int j = 0; j < m; j++) {
            int   cj = __shfl_sync(0xffffffffu, c, j);
            float nj = __shfl_sync(0xffffffffu, nv, j) * di;
            float2 hh = __ldg(&H2[cj * 32 + lane]);
            acc.x += hh.x * nj;
            acc.y += hh.y * nj;
        }
    }
    float2 bb = ((const float2*)bias)[lane];
    acc.x = fmaxf(acc.x + bb.x, 0.f);
    acc.y = fmaxf(acc.y + bb.y, 0.f);
    float2* outp = (DSTOUT == 0) ? (float2*)g_A : (float2*)outext;
    outp[i * 32 + lane] = acc;
}

// -------- launch --------
extern "C" void kernel_launch(void* const* d_in, const int* in_sizes, int n_in,
                              void* d_out, int out_size) {
    const float* x  = (const float*)d_in[0];
    const int*   ei = (const int*)d_in[1];
    const float* W0 = (const float*)d_in[2];
    const float* b0 = (const float*)d_in[3];
    const float* W1 = (const float*)d_in[4];
    const float* b1 = (const float*)d_in[5];
    const float* W2 = (const float*)d_in[6];
    const float* b2 = (const float*)d_in[7];
    float* out = (float*)d_out;

    int n = in_sizes[0] / D;
    int e = in_sizes[1] / 2;
    int nb = (n + 1023) / 1024;
    int e4 = (e + 3) / 4;

    int tile_blocks = (n + 63) / 64;
    int agg_blocks  = (n + 7) / 8;

    k_count<<<(e4 + 255) / 256, 256>>>(ei, e, n);
    k_scanA<<<nb, 1024>>>(n);
    k_scanC<<<(n + 255) / 256, 256>>>(n, e, nb);
    k_fill <<<(e4 + 255) / 256, 256>>>(ei, e, n);

    k_gemm<0><<<tile_blocks, 128>>>(x, W0, n);
    k_agg<0> <<<agg_blocks, 256>>>(b0, nullptr, n);
    k_gemm<1><<<tile_blocks, 128>>>(nullptr, W1, n);
    k_agg<0> <<<agg_blocks, 256>>>(b1, nullptr, n);
    k_gemm<1><<<tile_blocks, 128>>>(nullptr, W2, n);
    k_agg<1> <<<agg_blocks, 256>>>(b2, out, n);
}

// round 12
// speedup vs baseline: 1.3158x; 1.0100x over previous
#include <cuda_runtime.h>
#include <cuda_bf16.h>
#include <cstdint>

#define D 64
#define N_MAX 131072
#define E_MAX 2097152

// -------- device scratch --------
__device__ float g_H[N_MAX * D];
__device__ float g_A[N_MAX * D];
__device__ int   g_cnt[N_MAX];      // statically zero; re-zeroed by k_scanA each run
__device__ float g_dinv[N_MAX];
__device__ int   g_rowtmp[N_MAX];
__device__ int   g_rowptr[N_MAX + 1];
__device__ int   g_cursor[N_MAX];   // seeded to rowptr by k_scanC each run
__device__ int   g_part[256];
__device__ int2  g_edge[E_MAX];     // {src col, dinv[src] bits}

__device__ __forceinline__ float tf32f(float f) {
    uint32_t r;
    asm("cvt.rna.tf32.f32 %0, %1;" : "=r"(r) : "f"(f));
    return __uint_as_float(r);
}

// per-block edge dtype probe: int64 buffer (values < 2^31) has zero odd slots
__device__ __forceinline__ int probe_elw(const int* __restrict__ p) {
    int nz = 0;
#pragma unroll
    for (int k = 0; k < 16; k++) nz |= p[2 * k + 1];
    return nz ? 1 : 2;
}

// -------- degree count: 4 edges/thread, REDG (no return) --------
__global__ void k_count(const int* __restrict__ p, int e, int n) {
    __shared__ int selw;
    if (threadIdx.x == 0) selw = probe_elw(p);
    __syncthreads();
    int elw = selw;
    int base = (blockIdx.x * blockDim.x + threadIdx.x) * 4;
    if (base >= e) return;
    int d[4];
    bool full = (base + 3 < e) && ((e & 3) == 0);
    if (elw == 1) {
        if (full) {
            int4 v = *(const int4*)(p + e + base);
            d[0] = v.x; d[1] = v.y; d[2] = v.z; d[3] = v.w;
        } else {
            for (int i = 0; i < 4; i++) d[i] = (base + i < e) ? p[e + base + i] : -1;
        }
    } else {
        const long long* q = (const long long*)p;
        if (full) {
            longlong2 v0 = *(const longlong2*)(q + e + base);
            longlong2 v1 = *(const longlong2*)(q + e + base + 2);
            d[0] = (int)v0.x; d[1] = (int)v0.y; d[2] = (int)v1.x; d[3] = (int)v1.y;
        } else {
            for (int i = 0; i < 4; i++) d[i] = (base + i < e) ? (int)q[e + base + i] : -1;
        }
    }
#pragma unroll
    for (int i = 0; i < 4; i++)
        if ((unsigned)d[i] < (unsigned)n) atomicAdd(&g_cnt[d[i]], 1);
}

// -------- scan A: warp-shuffle block scan + dinv + cnt reset --------
__global__ void __launch_bounds__(1024) k_scanA(int n) {
    __shared__ int wsum[32];
    int i = blockIdx.x * 1024 + threadIdx.x;
    int v = (i < n) ? g_cnt[i] : 0;
    if (i < n) {
        g_dinv[i] = rsqrtf((float)(v + 1));
        g_cnt[i] = 0;   // reset for next graph replay
    }
    int lane = threadIdx.x & 31, w = threadIdx.x >> 5;

    int x = v;
#pragma unroll
    for (int off = 1; off < 32; off <<= 1) {
        int t = __shfl_up_sync(0xffffffffu, x, off);
        if (lane >= off) x += t;
    }
    if (lane == 31) wsum[w] = x;
    __syncthreads();
    if (w == 0) {
        int s = wsum[lane];
        int t = s;
#pragma unroll
        for (int off = 1; off < 32; off <<= 1) {
            int u = __shfl_up_sync(0xffffffffu, t, off);
            if (lane >= off) t += u;
        }
        wsum[lane] = t - s;
        if (lane == 31) g_part[blockIdx.x] = t;
    }
    __syncthreads();
    if (i < n) g_rowtmp[i] = x - v + wsum[w];
}

// -------- scan C: local scan of partials; writes rowptr AND cursor --------
__global__ void k_scanC(int n, int e, int nb) {
    __shared__ int sh[128];
    __shared__ int ex[128];
    int t = threadIdx.x & 127;
    int v = (t < nb) ? g_part[t] : 0;
    sh[t] = v;
    __syncthreads();
#pragma unroll
    for (int off = 1; off < 128; off <<= 1) {
        int u = (t >= off) ? sh[t - off] : 0;
        __syncthreads();
        sh[t] += u;
        __syncthreads();
    }
    ex[t] = sh[t] - v;
    __syncthreads();

    int i = blockIdx.x * blockDim.x + threadIdx.x;
    if (i < n) {
        int rp = g_rowtmp[i] + ex[i >> 10];
        g_rowptr[i] = rp;
        g_cursor[i] = rp;
    }
    if (i == 0) g_rowptr[n] = e;
}

// -------- CSR fill: 4 edges/thread; single atomic per edge; stores dinv[src] --------
__global__ void k_fill(const int* __restrict__ p, int e, int n) {
    __shared__ int selw;
    if (threadIdx.x == 0) selw = probe_elw(p);
    __syncthreads();
    int elw = selw;
    int base = (blockIdx.x * blockDim.x + threadIdx.x) * 4;
    if (base >= e) return;
    int s[4], d[4];
    bool full = (base + 3 < e) && ((e & 3) == 0);
    if (elw == 1) {
        if (full) {
            int4 vs = *(const int4*)(p + base);
            int4 vd = *(const int4*)(p + e + base);
            s[0] = vs.x; s[1] = vs.y; s[2] = vs.z; s[3] = vs.w;
            d[0] = vd.x; d[1] = vd.y; d[2] = vd.z; d[3] = vd.w;
        } else {
            for (int i = 0; i < 4; i++) {
                s[i] = (base + i < e) ? p[base + i] : -1;
                d[i] = (base + i < e) ? p[e + base + i] : -1;
            }
        }
    } else {
        const long long* q = (const long long*)p;
        if (full) {
            longlong2 s0 = *(const longlong2*)(q + base);
            longlong2 s1 = *(const longlong2*)(q + base + 2);
            longlong2 d0 = *(const longlong2*)(q + e + base);
            longlong2 d1 = *(const longlong2*)(q + e + base + 2);
            s[0] = (int)s0.x; s[1] = (int)s0.y; s[2] = (int)s1.x; s[3] = (int)s1.y;
            d[0] = (int)d0.x; d[1] = (int)d0.y; d[2] = (int)d1.x; d[3] = (int)d1.y;
        } else {
            for (int i = 0; i < 4; i++) {
                s[i] = (base + i < e) ? (int)q[base + i] : -1;
                d[i] = (base + i < e) ? (int)q[e + base + i] : -1;
            }
        }
    }
#pragma unroll
    for (int i = 0; i < 4; i++) {
        if ((unsigned)s[i] < (unsigned)n && (unsigned)d[i] < (unsigned)n) {
            int pos = atomicAdd(&g_cursor[d[i]], 1);
            g_edge[pos] = make_int2(s[i], __float_as_int(g_dinv[s[i]]));
        }
    }
}

// -------- GEMM: g_H[n,64] = A[n,64] @ W[64,64] via tf32 mma.sync --------
template <int SRC>
__global__ void __launch_bounds__(128) k_gemm(const float* __restrict__ Aext,
                                              const float* __restrict__ W, int n) {
    __shared__ float As[64][68];
    __shared__ float Ws[64][72];

    const float* A = (SRC == 0) ? Aext : (const float*)g_A;
    int tid = threadIdx.x;
    int rowbase = blockIdx.x * 64;

#pragma unroll
    for (int i = 0; i < 8; i++) {
        int idx = tid + i * 128;
        int r = idx >> 4, f4 = idx & 15;
        float4 va = (rowbase + r < n)
            ? *(const float4*)(A + (size_t)(rowbase + r) * 64 + f4 * 4)
            : make_float4(0.f, 0.f, 0.f, 0.f);
        As[r][f4 * 4 + 0] = tf32f(va.x); As[r][f4 * 4 + 1] = tf32f(va.y);
        As[r][f4 * 4 + 2] = tf32f(va.z); As[r][f4 * 4 + 3] = tf32f(va.w);
        float4 vw = *(const float4*)(W + r * 64 + f4 * 4);
        Ws[r][f4 * 4 + 0] = tf32f(vw.x); Ws[r][f4 * 4 + 1] = tf32f(vw.y);
        Ws[r][f4 * 4 + 2] = tf32f(vw.z); Ws[r][f4 * 4 + 3] = tf32f(vw.w);
    }
    __syncthreads();

    int warp = tid >> 5, lane = tid & 31;
    int gid = lane >> 2, tig = lane & 3;
    int ar0 = warp * 16 + gid, ar1 = ar0 + 8;

    float acc[8][4];
#pragma unroll
    for (int t = 0; t < 8; t++)
#pragma unroll
        for (int c = 0; c < 4; c++) acc[t][c] = 0.f;

#pragma unroll
    for (int ks = 0; ks < 8; ks++) {
        int k0 = ks * 8;
        uint32_t a0 = __float_as_uint(As[ar0][k0 + tig]);
        uint32_t a1 = __float_as_uint(As[ar1][k0 + tig]);
        uint32_t a2 = __float_as_uint(As[ar0][k0 + tig + 4]);
        uint32_t a3 = __float_as_uint(As[ar1][k0 + tig + 4]);
#pragma unroll
        for (int nt = 0; nt < 8; nt++) {
            uint32_t b0 = __float_as_uint(Ws[k0 + tig][nt * 8 + gid]);
            uint32_t b1 = __float_as_uint(Ws[k0 + tig + 4][nt * 8 + gid]);
            asm volatile(
                "mma.sync.aligned.m16n8k8.row.col.f32.tf32.tf32.f32 "
                "{%0,%1,%2,%3}, {%4,%5,%6,%7}, {%8,%9}, {%0,%1,%2,%3};"
                : "+f"(acc[nt][0]), "+f"(acc[nt][1]), "+f"(acc[nt][2]), "+f"(acc[nt][3])
                : "r"(a0), "r"(a1), "r"(a2), "r"(a3), "r"(b0), "r"(b1));
        }
    }

    int row0 = rowbase + warp * 16 + gid, row1 = row0 + 8;
#pragma unroll
    for (int nt = 0; nt < 8; nt++) {
        int col = nt * 8 + tig * 2;
        if (row0 < n)
            *(float2*)(g_H + (size_t)row0 * 64 + col) = make_float2(acc[nt][0], acc[nt][1]);
        if (row1 < n)
            *(float2*)(g_H + (size_t)row1 * 64 + col) = make_float2(acc[nt][2], acc[nt][3]);
    }
}

// -------- Aggregation (warp per node; di factored out of inner loop) --------
// acc = di * ( sum_j dinv[src_j]*H[src_j] + di*H[i] ) + b, then relu
template <int DSTOUT>
__global__ void k_agg(const float* __restrict__ bias, float* __restrict__ outext,
                      int n) {
    int gw = (blockIdx.x * blockDim.x + threadIdx.x) >> 5;
    int lane = threadIdx.x & 31;
    if (gw >= n) return;
    int i = gw;

    const float2* H2 = (const float2*)g_H;
    float di = g_dinv[i];
    float2 h = H2[i * 32 + lane];
    float2 acc = make_float2(h.x * di, h.y * di);

    int s = g_rowptr[i], e = g_rowptr[i + 1];
    for (int base = s; base < e; base += 32) {
        int m = min(32, e - base);
        int c = 0; float nv = 0.f;
        if (lane < m) {
            int2 ed = g_edge[base + lane];
            c = ed.x; nv = __int_as_float(ed.y);   // dinv[src]
        }
#pragma unroll 4
        for (int j = 0; j < m; j++) {
            int   cj = __shfl_sync(0xffffffffu, c, j);
            float nj = __shfl_sync(0xffffffffu, nv, j);
            float2 hh = __ldg(&H2[cj * 32 + lane]);
            acc.x += hh.x * nj;
            acc.y += hh.y * nj;
        }
    }
    float2 bb = ((const float2*)bias)[lane];
    acc.x = fmaxf(acc.x * di + bb.x, 0.f);
    acc.y = fmaxf(acc.y * di + bb.y, 0.f);
    float2* outp = (DSTOUT == 0) ? (float2*)g_A : (float2*)outext;
    outp[i * 32 + lane] = acc;
}

// -------- launch --------
extern "C" void kernel_launch(void* const* d_in, const int* in_sizes, int n_in,
                              void* d_out, int out_size) {
    const float* x  = (const float*)d_in[0];
    const int*   ei = (const int*)d_in[1];
    const float* W0 = (const float*)d_in[2];
    const float* b0 = (const float*)d_in[3];
    const float* W1 = (const float*)d_in[4];
    const float* b1 = (const float*)d_in[5];
    const float* W2 = (const float*)d_in[6];
    const float* b2 = (const float*)d_in[7];
    float* out = (float*)d_out;

    int n = in_sizes[0] / D;
    int e = in_sizes[1] / 2;
    int nb = (n + 1023) / 1024;
    int e4 = (e + 3) / 4;

    int tile_blocks = (n + 63) / 64;
    int agg_blocks  = (n + 7) / 8;

    // host-side stream/event objects (created once, before first capture)
    static cudaStream_t s2 = nullptr;
    static cudaEvent_t ev_fork = nullptr, ev_g0 = nullptr;
    if (!s2) {
        cudaStreamCreateWithFlags(&s2, cudaStreamNonBlocking);
        cudaEventCreateWithFlags(&ev_fork, cudaEventDisableTiming);
        cudaEventCreateWithFlags(&ev_g0, cudaEventDisableTiming);
    }

    // fork GEMM0 (x @ W0 -> g_H): independent of the CSR build
    cudaEventRecord(ev_fork, 0);
    cudaStreamWaitEvent(s2, ev_fork, 0);
    k_gemm<0><<<tile_blocks, 128, 0, s2>>>(x, W0, n);
    cudaEventRecord(ev_g0, s2);

    // CSR build chain
    k_count<<<(e4 + 255) / 256, 256>>>(ei, e, n);
    k_scanA<<<nb, 1024>>>(n);
    k_scanC<<<(n + 255) / 256, 256>>>(n, e, nb);
    k_fill <<<(e4 + 255) / 256, 256>>>(ei, e, n);

    // join, then layers
    cudaStreamWaitEvent(0, ev_g0, 0);
    k_agg<0> <<<agg_blocks, 256>>>(b0, nullptr, n);
    k_gemm<1><<<tile_blocks, 128>>>(nullptr, W1, n);
    k_agg<0> <<<agg_blocks, 256>>>(b1, nullptr, n);
    k_gemm<1><<<tile_blocks, 128>>>(nullptr, W2, n);
    k_agg<1> <<<agg_blocks, 256>>>(b2, out, n);
}

// round 14
// speedup vs baseline: 1.3464x; 1.0233x over previous
#include <cuda_runtime.h>
#include <cuda_bf16.h>
#include <cstdint>

#define D 64
#define N_MAX 131072
#define E_MAX 2097152

// -------- device scratch --------
__device__ float g_H[N_MAX * D];    // post-GEMM features, pre-scaled by dinv[row]
__device__ float g_A[N_MAX * D];    // activations
__device__ int   g_cnt[N_MAX];      // statically zero; re-zeroed by k_scanA each run
__device__ float g_dinv[N_MAX];
__device__ int   g_rowtmp[N_MAX];
__device__ int   g_rowptr[N_MAX + 1];
__device__ int   g_cursor[N_MAX];   // seeded to rowptr by k_scanC each run
__device__ int   g_part[256];
__device__ int   g_col[E_MAX];      // src index only (4B payload)

__device__ __forceinline__ float tf32f(float f) {
    uint32_t r;
    asm("cvt.rna.tf32.f32 %0, %1;" : "=r"(r) : "f"(f));
    return __uint_as_float(r);
}

// per-block edge dtype probe: int64 buffer (values < 2^31) has zero odd slots
__device__ __forceinline__ int probe_elw(const int* __restrict__ p) {
    int nz = 0;
#pragma unroll
    for (int k = 0; k < 16; k++) nz |= p[2 * k + 1];
    return nz ? 1 : 2;
}

// -------- degree count: 4 edges/thread, REDG (no return) --------
__global__ void k_count(const int* __restrict__ p, int e, int n) {
    __shared__ int selw;
    if (threadIdx.x == 0) selw = probe_elw(p);
    __syncthreads();
    int elw = selw;
    int base = (blockIdx.x * blockDim.x + threadIdx.x) * 4;
    if (base >= e) return;
    int d[4];
    bool full = (base + 3 < e) && ((e & 3) == 0);
    if (elw == 1) {
        if (full) {
            int4 v = *(const int4*)(p + e + base);
            d[0] = v.x; d[1] = v.y; d[2] = v.z; d[3] = v.w;
        } else {
            for (int i = 0; i < 4; i++) d[i] = (base + i < e) ? p[e + base + i] : -1;
        }
    } else {
        const long long* q = (const long long*)p;
        if (full) {
            longlong2 v0 = *(const longlong2*)(q + e + base);
            longlong2 v1 = *(const longlong2*)(q + e + base + 2);
            d[0] = (int)v0.x; d[1] = (int)v0.y; d[2] = (int)v1.x; d[3] = (int)v1.y;
        } else {
            for (int i = 0; i < 4; i++) d[i] = (base + i < e) ? (int)q[e + base + i] : -1;
        }
    }
#pragma unroll
    for (int i = 0; i < 4; i++)
        if ((unsigned)d[i] < (unsigned)n) atomicAdd(&g_cnt[d[i]], 1);
}

// -------- scan A: warp-shuffle block scan + dinv + cnt reset --------
__global__ void __launch_bounds__(1024) k_scanA(int n) {
    __shared__ int wsum[32];
    int i = blockIdx.x * 1024 + threadIdx.x;
    int v = (i < n) ? g_cnt[i] : 0;
    if (i < n) {
        g_dinv[i] = rsqrtf((float)(v + 1));
        g_cnt[i] = 0;   // reset for next graph replay
    }
    int lane = threadIdx.x & 31, w = threadIdx.x >> 5;

    int x = v;
#pragma unroll
    for (int off = 1; off < 32; off <<= 1) {
        int t = __shfl_up_sync(0xffffffffu, x, off);
        if (lane >= off) x += t;
    }
    if (lane == 31) wsum[w] = x;
    __syncthreads();
    if (w == 0) {
        int s = wsum[lane];
        int t = s;
#pragma unroll
        for (int off = 1; off < 32; off <<= 1) {
            int u = __shfl_up_sync(0xffffffffu, t, off);
            if (lane >= off) t += u;
        }
        wsum[lane] = t - s;
        if (lane == 31) g_part[blockIdx.x] = t;
    }
    __syncthreads();
    if (i < n) g_rowtmp[i] = x - v + wsum[w];
}

// -------- scan C: local scan of partials; writes rowptr AND cursor --------
__global__ void k_scanC(int n, int e, int nb) {
    __shared__ int sh[128];
    __shared__ int ex[128];
    int t = threadIdx.x & 127;
    int v = (t < nb) ? g_part[t] : 0;
    sh[t] = v;
    __syncthreads();
#pragma unroll
    for (int off = 1; off < 128; off <<= 1) {
        int u = (t >= off) ? sh[t - off] : 0;
        __syncthreads();
        sh[t] += u;
        __syncthreads();
    }
    ex[t] = sh[t] - v;
    __syncthreads();

    int i = blockIdx.x * blockDim.x + threadIdx.x;
    if (i < n) {
        int rp = g_rowtmp[i] + ex[i >> 10];
        g_rowptr[i] = rp;
        g_cursor[i] = rp;
    }
    if (i == 0) g_rowptr[n] = e;
}

// -------- CSR fill: 4 edges/thread; single atomic per edge; 4B payload --------
__global__ void k_fill(const int* __restrict__ p, int e, int n) {
    __shared__ int selw;
    if (threadIdx.x == 0) selw = probe_elw(p);
    __syncthreads();
    int elw = selw;
    int base = (blockIdx.x * blockDim.x + threadIdx.x) * 4;
    if (base >= e) return;
    int s[4], d[4];
    bool full = (base + 3 < e) && ((e & 3) == 0);
    if (elw == 1) {
        if (full) {
            int4 vs = *(const int4*)(p + base);
            int4 vd = *(const int4*)(p + e + base);
            s[0] = vs.x; s[1] = vs.y; s[2] = vs.z; s[3] = vs.w;
            d[0] = vd.x; d[1] = vd.y; d[2] = vd.z; d[3] = vd.w;
        } else {
            for (int i = 0; i < 4; i++) {
                s[i] = (base + i < e) ? p[base + i] : -1;
                d[i] = (base + i < e) ? p[e + base + i] : -1;
            }
        }
    } else {
        const long long* q = (const long long*)p;
        if (full) {
            longlong2 s0 = *(const longlong2*)(q + base);
            longlong2 s1 = *(const longlong2*)(q + base + 2);
            longlong2 d0 = *(const longlong2*)(q + e + base);
            longlong2 d1 = *(const longlong2*)(q + e + base + 2);
            s[0] = (int)s0.x; s[1] = (int)s0.y; s[2] = (int)s1.x; s[3] = (int)s1.y;
            d[0] = (int)d0.x; d[1] = (int)d0.y; d[2] = (int)d1.x; d[3] = (int)d1.y;
        } else {
            for (int i = 0; i < 4; i++) {
                s[i] = (base + i < e) ? (int)q[base + i] : -1;
                d[i] = (base + i < e) ? (int)q[e + base + i] : -1;
            }
        }
    }
#pragma unroll
    for (int i = 0; i < 4; i++) {
        if ((unsigned)s[i] < (unsigned)n && (unsigned)d[i] < (unsigned)n) {
            int pos = atomicAdd(&g_cursor[d[i]], 1);
            g_col[pos] = s[i];
        }
    }
}

// -------- GEMM: g_H[r,:] = dinv[r] * (A[r,:] @ W) via tf32 mma.sync --------
template <int SRC>
__global__ void __launch_bounds__(128) k_gemm(const float* __restrict__ Aext,
                                              const float* __restrict__ W, int n) {
    __shared__ float As[64][68];
    __shared__ float Ws[64][72];

    const float* A = (SRC == 0) ? Aext : (const float*)g_A;
    int tid = threadIdx.x;
    int rowbase = blockIdx.x * 64;

#pragma unroll
    for (int i = 0; i < 8; i++) {
        int idx = tid + i * 128;
        int r = idx >> 4, f4 = idx & 15;
        float4 va = (rowbase + r < n)
            ? *(const float4*)(A + (size_t)(rowbase + r) * 64 + f4 * 4)
            : make_float4(0.f, 0.f, 0.f, 0.f);
        As[r][f4 * 4 + 0] = tf32f(va.x); As[r][f4 * 4 + 1] = tf32f(va.y);
        As[r][f4 * 4 + 2] = tf32f(va.z); As[r][f4 * 4 + 3] = tf32f(va.w);
        float4 vw = *(const float4*)(W + r * 64 + f4 * 4);
        Ws[r][f4 * 4 + 0] = tf32f(vw.x); Ws[r][f4 * 4 + 1] = tf32f(vw.y);
        Ws[r][f4 * 4 + 2] = tf32f(vw.z); Ws[r][f4 * 4 + 3] = tf32f(vw.w);
    }
    __syncthreads();

    int warp = tid >> 5, lane = tid & 31;
    int gid = lane >> 2, tig = lane & 3;
    int ar0 = warp * 16 + gid, ar1 = ar0 + 8;

    float acc[8][4];
#pragma unroll
    for (int t = 0; t < 8; t++)
#pragma unroll
        for (int c = 0; c < 4; c++) acc[t][c] = 0.f;

#pragma unroll
    for (int ks = 0; ks < 8; ks++) {
        int k0 = ks * 8;
        uint32_t a0 = __float_as_uint(As[ar0][k0 + tig]);
        uint32_t a1 = __float_as_uint(As[ar1][k0 + tig]);
        uint32_t a2 = __float_as_uint(As[ar0][k0 + tig + 4]);
        uint32_t a3 = __float_as_uint(As[ar1][k0 + tig + 4]);
#pragma unroll
        for (int nt = 0; nt < 8; nt++) {
            uint32_t b0 = __float_as_uint(Ws[k0 + tig][nt * 8 + gid]);
            uint32_t b1 = __float_as_uint(Ws[k0 + tig + 4][nt * 8 + gid]);
            asm volatile(
                "mma.sync.aligned.m16n8k8.row.col.f32.tf32.tf32.f32 "
                "{%0,%1,%2,%3}, {%4,%5,%6,%7}, {%8,%9}, {%0,%1,%2,%3};"
                : "+f"(acc[nt][0]), "+f"(acc[nt][1]), "+f"(acc[nt][2]), "+f"(acc[nt][3])
                : "r"(a0), "r"(a1), "r"(a2), "r"(a3), "r"(b0), "r"(b1));
        }
    }

    int row0 = rowbase + warp * 16 + gid, row1 = row0 + 8;
    float s0 = (row0 < n) ? g_dinv[row0] : 0.f;
    float s1 = (row1 < n) ? g_dinv[row1] : 0.f;
#pragma unroll
    for (int nt = 0; nt < 8; nt++) {
        int col = nt * 8 + tig * 2;
        if (row0 < n)
            *(float2*)(g_H + (size_t)row0 * 64 + col) =
                make_float2(acc[nt][0] * s0, acc[nt][1] * s0);
        if (row1 < n)
            *(float2*)(g_H + (size_t)row1 * 64 + col) =
                make_float2(acc[nt][2] * s1, acc[nt][3] * s1);
    }
}

// -------- Aggregation: acc = H'[i] + sum_j H'[src_j]; out = relu(di*acc + b) --------
template <int DSTOUT>
__global__ void k_agg(const float* __restrict__ bias, float* __restrict__ outext,
                      int n) {
    int gw = (blockIdx.x * blockDim.x + threadIdx.x) >> 5;
    int lane = threadIdx.x & 31;
    if (gw >= n) return;
    int i = gw;

    const float2* H2 = (const float2*)g_H;
    float di = g_dinv[i];
    float2 acc = H2[i * 32 + lane];   // self term: H'_i = dinv_i * H_i (pre-scaled)

    int s = g_rowptr[i], e = g_rowptr[i + 1];
    for (int base = s; base < e; base += 32) {
        int m = min(32, e - base);
        int c = (lane < m) ? g_col[base + lane] : 0;
#pragma unroll 4
        for (int j = 0; j < m; j++) {
            int cj = __shfl_sync(0xffffffffu, c, j);
            float2 hh = __ldg(&H2[cj * 32 + lane]);
            acc.x += hh.x;
            acc.y += hh.y;
        }
    }
    float2 bb = ((const float2*)bias)[lane];
    acc.x = fmaxf(acc.x * di + bb.x, 0.f);
    acc.y = fmaxf(acc.y * di + bb.y, 0.f);
    float2* outp = (DSTOUT == 0) ? (float2*)g_A : (float2*)outext;
    outp[i * 32 + lane] = acc;
}

// -------- launch: single stream, fully serial --------
extern "C" void kernel_launch(void* const* d_in, const int* in_sizes, int n_in,
                              void* d_out, int out_size) {
    const float* x  = (const float*)d_in[0];
    const int*   ei = (const int*)d_in[1];
    const float* W0 = (const float*)d_in[2];
    const float* b0 = (const float*)d_in[3];
    const float* W1 = (const float*)d_in[4];
    const float* b1 = (const float*)d_in[5];
    const float* W2 = (const float*)d_in[6];
    const float* b2 = (const float*)d_in[7];
    float* out = (float*)d_out;

    int n = in_sizes[0] / D;
    int e = in_sizes[1] / 2;
    int nb = (n + 1023) / 1024;
    int e4 = (e + 3) / 4;

    int tile_blocks = (n + 63) / 64;
    int agg_blocks  = (n + 7) / 8;

    k_count<<<(e4 + 255) / 256, 256>>>(ei, e, n);
    k_scanA<<<nb, 1024>>>(n);
    k_scanC<<<(n + 255) / 256, 256>>>(n, e, nb);
    k_fill <<<(e4 + 255) / 256, 256>>>(ei, e, n);

    k_gemm<0><<<tile_blocks, 128>>>(x, W0, n);
    k_agg<0> <<<agg_blocks, 256>>>(b0, nullptr, n);
    k_gemm<1><<<tile_blocks, 128>>>(nullptr, W1, n);
    k_agg<0> <<<agg_blocks, 256>>>(b1, nullptr, n);
    k_gemm<1><<<tile_blocks, 128>>>(nullptr, W2, n);
    k_agg<1> <<<agg_blocks, 256>>>(b2, out, n);
}